// round 16
// baseline (speedup 1.0000x reference)
#include <cuda_runtime.h>
#include <cuda_fp16.h>
#include <math.h>

#define NN 50000
#define EE 800000
#define GG 256
#define EPSF 1e-5f
#define SCAN_B 196   // ceil(50000/256)

// ---------------- scratch ----------------------------------------------------
__device__ __align__(256) __half g_ya[NN * 64];     // message ping buffer
__device__ __align__(256) __half g_yb[NN * 64];     // message pong buffer
__device__ __align__(256) float  g_dis[NN];
__device__ __align__(256) float  g_rs[NN];          // dis*(dis + sum dis[src])
__device__ __align__(256) float2 g_td[NN];          // (x*dis, dis)
__device__ __align__(256) int    g_cnt[NN];
__device__ __align__(256) int    g_rowptr[NN + 1];
__device__ __align__(256) int    g_cur[NN];
__device__ __align__(256) int    g_csr[EE];
__device__ __align__(256) int    g_bsum[SCAN_B];
__device__ __align__(256) float  g_stats[384];
__device__ __align__(256) float  g_pool[GG * 128];

__device__ __forceinline__ float geluf(float x) {
    return 0.5f * x * (1.0f + erff(x * 0.70710678118654752f));
}
__device__ __forceinline__ void red_add_v4(float* addr, float a, float b, float c, float d) {
    asm volatile("red.global.add.v4.f32 [%0], {%1,%2,%3,%4};"
                 :: "l"(addr), "f"(a), "f"(b), "f"(c), "f"(d) : "memory");
}
// accumulate 8 half-channels from one uint4
__device__ __forceinline__ void acc_h8(float* s, uint4 u) {
    float2 f0 = __half22float2(*(__half2*)&u.x);
    float2 f1 = __half22float2(*(__half2*)&u.y);
    float2 f2 = __half22float2(*(__half2*)&u.z);
    float2 f3 = __half22float2(*(__half2*)&u.w);
    s[0] += f0.x; s[1] += f0.y; s[2] += f1.x; s[3] += f1.y;
    s[4] += f2.x; s[5] += f2.y; s[6] += f3.x; s[7] += f3.y;
}

// ---------------- CSR build ---------------------------------------------------
__global__ void k_hist(const int* __restrict__ ei) {
    int e = blockIdx.x * blockDim.x + threadIdx.x;
    if (e < EE) atomicAdd(&g_cnt[ei[EE + e]], 1);
}
__global__ void k_scanA() {
    __shared__ int sh[256];
    int i = blockIdx.x * 256 + threadIdx.x;
    sh[threadIdx.x] = (i < NN) ? g_cnt[i] : 0;
    __syncthreads();
    for (int o = 128; o > 0; o >>= 1) {
        if (threadIdx.x < o) sh[threadIdx.x] += sh[threadIdx.x + o];
        __syncthreads();
    }
    if (threadIdx.x == 0) g_bsum[blockIdx.x] = sh[0];
}
__global__ void k_scanB() {
    __shared__ int sh[256];
    int t = threadIdx.x;
    int v = (t < SCAN_B) ? g_bsum[t] : 0;
    sh[t] = v;
    __syncthreads();
    for (int o = 1; o < 256; o <<= 1) {
        int u = (t >= o) ? sh[t - o] : 0;
        __syncthreads();
        sh[t] += u;
        __syncthreads();
    }
    if (t < SCAN_B) g_bsum[t] = sh[t] - v;
    if (t == 0) g_rowptr[NN] = EE;
}
__global__ void k_scanC(const float* __restrict__ x) {
    __shared__ int sh[256];
    int i = blockIdx.x * 256 + threadIdx.x;
    int t = threadIdx.x;
    int c = (i < NN) ? g_cnt[i] : 0;
    sh[t] = c;
    __syncthreads();
    for (int o = 1; o < 256; o <<= 1) {
        int u = (t >= o) ? sh[t - o] : 0;
        __syncthreads();
        sh[t] += u;
        __syncthreads();
    }
    if (i < NN) {
        int rp = g_bsum[blockIdx.x] + sh[t] - c;
        g_rowptr[i] = rp;
        g_cur[i]    = rp;
        float d = rsqrtf((float)c + 1.0f);
        g_dis[i]  = d;
        g_td[i]   = make_float2(x[i] * d, d);
    }
}
__global__ void k_fill(const int* __restrict__ ei) {
    int e = blockIdx.x * blockDim.x + threadIdx.x;
    if (e < EE) {
        int pos = atomicAdd(&g_cur[ei[EE + e]], 1);
        g_csr[pos] = ei[e];
    }
}

// ---------------- layer 0: 2 threads/node gather; REDUX-aggregated stats ------
__global__ void __launch_bounds__(256) k_l0(const float* __restrict__ W1,
                                            const float* __restrict__ b1,
                                            float* __restrict__ statsOut) {
    __shared__ float sh[32];
    int tid = threadIdx.x;
    if (tid < 32) sh[tid] = 0.f;
    __syncthreads();

    int t = blockIdx.x * 256 + tid;
    int n = t >> 1, k = t & 1;
    bool valid = n < NN;
    float st = 0.f, sd = 0.f, d = 0.f;
    if (valid) {
        int rp = g_rowptr[n], re = g_rowptr[n + 1];
        int half = (re - rp) >> 1;
        int j    = k ? (rp + half) : rp;
        int jend = k ? re : (rp + half);
        if (k == 0) { float2 a = g_td[n]; st = a.x; sd = a.y; d = a.y; }
        for (; j + 4 <= jend; j += 4) {
            int i0 = g_csr[j], i1 = g_csr[j+1], i2 = g_csr[j+2], i3 = g_csr[j+3];
            float2 a0 = g_td[i0], a1 = g_td[i1], a2 = g_td[i2], a3 = g_td[i3];
            st += (a0.x + a1.x) + (a2.x + a3.x);
            sd += (a0.y + a1.y) + (a2.y + a3.y);
        }
        for (; j < jend; ++j) { float2 a = g_td[g_csr[j]]; st += a.x; sd += a.y; }
    }
    // combine edge-halves (lanes 2m, 2m+1)
    st += __shfl_down_sync(0xffffffffu, st, 1);
    sd += __shfl_down_sync(0xffffffffu, sd, 1);

    bool lead = valid && (k == 0);
    float u = 0.f;
    if (lead) {
        u = d * st;
        g_rs[n] = d * sd;
    }
    float vv[16];
    #pragma unroll
    for (int c = 0; c < 16; ++c)
        vv[c] = lead ? geluf(fmaf(__ldg(&W1[c]), u, __ldg(&b1[c]))) : 0.f;
    if (lead) {
        uint4 o0, o1;
        __half2 h;
        h = __floats2half2_rn(vv[0]*d,  vv[1]*d);  o0.x = *(unsigned*)&h;
        h = __floats2half2_rn(vv[2]*d,  vv[3]*d);  o0.y = *(unsigned*)&h;
        h = __floats2half2_rn(vv[4]*d,  vv[5]*d);  o0.z = *(unsigned*)&h;
        h = __floats2half2_rn(vv[6]*d,  vv[7]*d);  o0.w = *(unsigned*)&h;
        h = __floats2half2_rn(vv[8]*d,  vv[9]*d);  o1.x = *(unsigned*)&h;
        h = __floats2half2_rn(vv[10]*d, vv[11]*d); o1.y = *(unsigned*)&h;
        h = __floats2half2_rn(vv[12]*d, vv[13]*d); o1.z = *(unsigned*)&h;
        h = __floats2half2_rn(vv[14]*d, vv[15]*d); o1.w = *(unsigned*)&h;
        ((uint4*)&g_ya[n * 16])[0] = o0;
        ((uint4*)&g_ya[n * 16])[1] = o1;
    }
    // stats: uniform-address smem atomics -> ptxas REDUX.SUM aggregation
    #pragma unroll
    for (int c = 0; c < 16; ++c) {
        atomicAdd(&sh[c],      vv[c]);
        atomicAdd(&sh[16 + c], vv[c] * vv[c]);
    }
    __syncthreads();
    if (tid < 32) atomicAdd(&statsOut[tid], sh[tid]);
}

// ---------------- fused layer: uint4 (8-ch) gather -> smem -> W-hoisted mm -----
template<int Cin, int Cout, int TILE, bool POOL>
__global__ void __launch_bounds__(256) k_layer(
        const __half* __restrict__ yin, __half* __restrict__ yout,
        const float* __restrict__ W, const float* __restrict__ bias,
        const float* __restrict__ gam, const float* __restrict__ bet,
        const float* __restrict__ statsIn, float* __restrict__ statsOut,
        const int* __restrict__ batch) {
    const int WQ8   = Cin / 8;           // uint4 groups per node row
    const int CQ    = Cout / 4;
    const int TPN   = 2 * WQ8;           // threads per node in gather
    const int NPB_A = 256 / TPN;         // nodes per gather pass
    const int PASSES = TILE / NPB_A;
    const int SLOTS = 256 / CQ;          // concurrent nodes in mm
    const int NITER = TILE / SLOTS;      // nodes per thread in mm
    __shared__ float sc[64], shf[64], sh[256];
    __shared__ float ut[TILE * Cin];     // <= 8 KB
    int tid = threadIdx.x;
    if (tid < Cin) {
        float mu  = statsIn[tid] * (1.0f / NN);
        float var = statsIn[Cin + tid] * (1.0f / NN) - mu * mu;
        float s = gam[tid] * rsqrtf(var + EPSF);
        sc[tid]  = s;
        shf[tid] = bet[tid] - mu * s;
    }
    if (!POOL) for (int i = tid; i < 2 * Cout; i += 256) sh[i] = 0.f;
    __syncthreads();

    int n0 = blockIdx.x * TILE;
    // ---- phase A: cooperative gather into ut (uint4 loads, 2-way edge split) --
    {
        int nodeA = tid / TPN;
        int rem   = tid - nodeA * TPN;
        int q8 = rem >> 1, k = rem & 1;
        const uint4* __restrict__ hw = (const uint4*)yin;
        #pragma unroll
        for (int p = 0; p < PASSES; ++p) {
            int nl = p * NPB_A + nodeA;
            int n  = n0 + nl;
            float s[8];
            #pragma unroll
            for (int c = 0; c < 8; ++c) s[c] = 0.f;
            if (n < NN) {
                int rp = g_rowptr[n], re = g_rowptr[n + 1];
                int half = (re - rp) >> 1;
                int j    = k ? (rp + half) : rp;
                int jend = k ? re : (rp + half);
                if (k == 0) acc_h8(s, hw[n * WQ8 + q8]);   // self term
                while (j < jend && (j & 3)) acc_h8(s, hw[g_csr[j++] * WQ8 + q8]);
                for (; j + 4 <= jend; j += 4) {
                    int4 a4 = *(const int4*)&g_csr[j];
                    uint4 u0 = hw[a4.x * WQ8 + q8];
                    uint4 u1 = hw[a4.y * WQ8 + q8];
                    uint4 u2 = hw[a4.z * WQ8 + q8];
                    uint4 u3 = hw[a4.w * WQ8 + q8];
                    acc_h8(s, u0); acc_h8(s, u1); acc_h8(s, u2); acc_h8(s, u3);
                }
                for (; j < jend; ++j) acc_h8(s, hw[g_csr[j] * WQ8 + q8]);
            }
            // combine the two edge-halves (lanes 2m, 2m+1)
            #pragma unroll
            for (int c = 0; c < 8; ++c)
                s[c] += __shfl_down_sync(0xffffffffu, s[c], 1);
            if (k == 0 && n < NN) {
                int ci = q8 * 8;
                float d = g_dis[n], rsv = g_rs[n];
                float* u = &ut[nl * Cin + ci];
                #pragma unroll
                for (int c = 0; c < 8; ++c)
                    u[c] = fmaf(shf[ci + c], rsv, sc[ci + c] * (s[c] * d));
            } else if (k == 0) {
                int ci = q8 * 8;
                float* u = &ut[nl * Cin + ci];
                #pragma unroll
                for (int c = 0; c < 8; ++c) u[c] = 0.f;
            }
        }
    }
    __syncthreads();

    // ---- phase B: W-hoisted mm over NITER nodes per thread ----
    int c4 = tid % CQ, slot = tid / CQ;
    const float4* __restrict__ Wv = (const float4*)W;
    float4 bb = *(const float4*)&bias[c4 * 4];
    float4 acc[NITER];
    #pragma unroll
    for (int k = 0; k < NITER; ++k) acc[k] = bb;
    #pragma unroll 4
    for (int i = 0; i < Cin; ++i) {
        float4 w = Wv[i * CQ + c4];
        #pragma unroll
        for (int k = 0; k < NITER; ++k) {
            float av = ut[(slot + k * SLOTS) * Cin + i];
            acc[k].x = fmaf(av, w.x, acc[k].x);
            acc[k].y = fmaf(av, w.y, acc[k].y);
            acc[k].z = fmaf(av, w.z, acc[k].z);
            acc[k].w = fmaf(av, w.w, acc[k].w);
        }
    }
    float4 rsum = make_float4(0.f, 0.f, 0.f, 0.f);
    float4 r2sum = make_float4(0.f, 0.f, 0.f, 0.f);
    #pragma unroll
    for (int k = 0; k < NITER; ++k) {
        int n = n0 + slot + k * SLOTS;
        if (n >= NN) continue;
        float4 r;
        r.x = geluf(acc[k].x); r.y = geluf(acc[k].y);
        r.z = geluf(acc[k].z); r.w = geluf(acc[k].w);
        if (POOL) {
            int g = batch[n];
            red_add_v4(&g_pool[g * 128 + c4 * 4], r.x, r.y, r.z, r.w);
        } else {
            float d = g_dis[n];
            __half2 h0 = __floats2half2_rn(r.x * d, r.y * d);
            __half2 h1 = __floats2half2_rn(r.z * d, r.w * d);
            uint2 u; u.x = *(unsigned*)&h0; u.y = *(unsigned*)&h1;
            ((uint2*)yout)[n * CQ + c4] = u;
            rsum.x += r.x; rsum.y += r.y; rsum.z += r.z; rsum.w += r.w;
            r2sum.x += r.x * r.x; r2sum.y += r.y * r.y;
            r2sum.z += r.z * r.z; r2sum.w += r.w * r.w;
        }
    }
    if (!POOL) {
        #pragma unroll
        for (int off = CQ; off < 32; off <<= 1) {
            rsum.x  += __shfl_down_sync(0xffffffffu, rsum.x,  off);
            rsum.y  += __shfl_down_sync(0xffffffffu, rsum.y,  off);
            rsum.z  += __shfl_down_sync(0xffffffffu, rsum.z,  off);
            rsum.w  += __shfl_down_sync(0xffffffffu, rsum.w,  off);
            r2sum.x += __shfl_down_sync(0xffffffffu, r2sum.x, off);
            r2sum.y += __shfl_down_sync(0xffffffffu, r2sum.y, off);
            r2sum.z += __shfl_down_sync(0xffffffffu, r2sum.z, off);
            r2sum.w += __shfl_down_sync(0xffffffffu, r2sum.w, off);
        }
        if ((tid & 31) < CQ) {
            int c0 = (tid % CQ) * 4;
            atomicAdd(&sh[c0 + 0], rsum.x);  atomicAdd(&sh[Cout + c0 + 0], r2sum.x);
            atomicAdd(&sh[c0 + 1], rsum.y);  atomicAdd(&sh[Cout + c0 + 1], r2sum.y);
            atomicAdd(&sh[c0 + 2], rsum.z);  atomicAdd(&sh[Cout + c0 + 2], r2sum.z);
            atomicAdd(&sh[c0 + 3], rsum.w);  atomicAdd(&sh[Cout + c0 + 3], r2sum.w);
        }
        __syncthreads();
        for (int i = tid; i < 2 * Cout; i += 256) atomicAdd(&statsOut[i], sh[i]);
    }
}

// ---------------- fused MLP head -------------------------------------------------
__global__ void k_head(const int* __restrict__ batch, const float* __restrict__ yx,
                       const float* __restrict__ lw1, const float* __restrict__ lb1,
                       const float* __restrict__ lw2, const float* __restrict__ lb2,
                       const float* __restrict__ lw3, const float* __restrict__ lb3,
                       const float* __restrict__ lw4, const float* __restrict__ lb4,
                       float* __restrict__ out) {
    int g = blockIdx.x, tid = threadIdx.x;
    __shared__ float z[136], a1[128], a2[64], a3[32];
    __shared__ int bounds[2];
    if (tid < 2) {
        int key = g + tid;
        int lo = 0, hi = NN;
        while (lo < hi) {
            int mid = (lo + hi) >> 1;
            if (batch[mid] < key) lo = mid + 1; else hi = mid;
        }
        bounds[tid] = lo;
    }
    __syncthreads();
    float inv = 1.0f / fmaxf((float)(bounds[1] - bounds[0]), 1.0f);
    for (int j = tid; j < 135; j += 128)
        z[j] = (j < 128) ? g_pool[g * 128 + j] * inv : yx[g * 7 + (j - 128)];
    __syncthreads();
    {
        float s = lb1[tid];
        #pragma unroll 5
        for (int i = 0; i < 135; ++i) s = fmaf(z[i], lw1[i * 128 + tid], s);
        a1[tid] = geluf(s);
    }
    __syncthreads();
    if (tid < 64) {
        float s = lb2[tid];
        #pragma unroll 8
        for (int i = 0; i < 128; ++i) s = fmaf(a1[i], lw2[i * 64 + tid], s);
        a2[tid] = geluf(s);
    }
    __syncthreads();
    if (tid < 32) {
        float s = lb3[tid];
        #pragma unroll 8
        for (int i = 0; i < 64; ++i) s = fmaf(a2[i], lw3[i * 32 + tid], s);
        a3[tid] = geluf(s);
    }
    __syncthreads();
    if (tid < 2) {
        float s = lb4[tid];
        #pragma unroll
        for (int i = 0; i < 32; ++i) s = fmaf(a3[i], lw4[i * 2 + tid], s);
        out[g * 2 + tid] = 1.0f / (1.0f + expf(-s));
    }
}

// ---------------- host -------------------------------------------------------------
static inline int gs(int n) { return (n + 255) / 256; }

extern "C" void kernel_launch(void* const* d_in, const int* in_sizes, int n_in,
                              void* d_out, int out_size) {
    const float* x     = (const float*)d_in[0];
    const int*   ei    = (const int*)d_in[1];
    const int*   batch = (const int*)d_in[2];
    const float* yx    = (const float*)d_in[3];
    const float* W[4]  = {(const float*)d_in[4], (const float*)d_in[6],
                          (const float*)d_in[8], (const float*)d_in[10]};
    const float* B[4]  = {(const float*)d_in[5], (const float*)d_in[7],
                          (const float*)d_in[9], (const float*)d_in[11]};
    const float* Gm[3] = {(const float*)d_in[12], (const float*)d_in[14], (const float*)d_in[16]};
    const float* Be[3] = {(const float*)d_in[13], (const float*)d_in[15], (const float*)d_in[17]};
    const float* LW[4] = {(const float*)d_in[18], (const float*)d_in[20],
                          (const float*)d_in[22], (const float*)d_in[24]};
    const float* LB[4] = {(const float*)d_in[19], (const float*)d_in[21],
                          (const float*)d_in[23], (const float*)d_in[25]};

    void *p_cnt, *p_pool, *p_stats, *p_ya, *p_yb;
    cudaGetSymbolAddress(&p_cnt,   g_cnt);
    cudaGetSymbolAddress(&p_pool,  g_pool);
    cudaGetSymbolAddress(&p_stats, g_stats);
    cudaGetSymbolAddress(&p_ya,    g_ya);
    cudaGetSymbolAddress(&p_yb,    g_yb);
    float* stats = (float*)p_stats;
    __half* ya = (__half*)p_ya;
    __half* yb = (__half*)p_yb;

    cudaMemsetAsync(p_cnt,   0, NN * sizeof(int));
    cudaMemsetAsync(p_pool,  0, GG * 128 * sizeof(float));
    cudaMemsetAsync(p_stats, 0, 384 * sizeof(float));

    k_hist <<<gs(EE), 256>>>(ei);
    k_scanA<<<SCAN_B, 256>>>();
    k_scanB<<<1, 256>>>();
    k_scanC<<<SCAN_B, 256>>>(x);
    k_fill <<<gs(EE), 256>>>(ei);

    // layer 0: 2 threads/node scalar gather -> ya fp16[16] + rs + stats0
    k_l0<<<gs(NN * 2), 256>>>(W[0], B[0], stats + 0);

    // fused layers, uint4 gathers (ping-pong message buffers)
    k_layer<16, 32, 64, false><<<(NN + 63) / 64, 256>>>(ya, yb, W[1], B[1], Gm[0], Be[0],
                                                        stats + 0, stats + 128, batch);
    k_layer<32, 64, 32, false><<<(NN + 31) / 32, 256>>>(yb, ya, W[2], B[2], Gm[1], Be[1],
                                                        stats + 128, stats + 256, batch);
    k_layer<64, 128, 32, true><<<(NN + 31) / 32, 256>>>(ya, yb, W[3], B[3], Gm[2], Be[2],
                                                        stats + 256, nullptr, batch);

    k_head<<<GG, 128>>>(batch, yx, LW[0], LB[0], LW[1], LB[1],
                        LW[2], LB[2], LW[3], LB[3], (float*)d_out);
}

// round 17
// speedup vs baseline: 1.2570x; 1.2570x over previous
#include <cuda_runtime.h>
#include <cuda_fp16.h>
#include <math.h>

#define NN 50000
#define EE 800000
#define GG 256
#define EPSF 1e-5f
#define SCAN_B 196   // ceil(50000/256)

// ---------------- scratch ----------------------------------------------------
__device__ __align__(256) __half g_ya[NN * 64];     // message ping buffer
__device__ __align__(256) __half g_yb[NN * 64];     // message pong buffer
__device__ __align__(256) float  g_dis[NN];
__device__ __align__(256) float  g_rs[NN];          // dis*(dis + sum dis[src])
__device__ __align__(256) float2 g_td[NN];          // (x*dis, dis)
__device__ __align__(256) int    g_cnt[NN];
__device__ __align__(256) int    g_rowptr[NN + 1];
__device__ __align__(256) int    g_cur[NN];
__device__ __align__(256) int    g_csr[EE];
__device__ __align__(256) int    g_bsum[SCAN_B];
__device__ __align__(256) float  g_stats[384];
__device__ __align__(256) float  g_pool[GG * 128];

__device__ __forceinline__ float geluf(float x) {
    return 0.5f * x * (1.0f + erff(x * 0.70710678118654752f));
}
__device__ __forceinline__ void red_add_v4(float* addr, float a, float b, float c, float d) {
    asm volatile("red.global.add.v4.f32 [%0], {%1,%2,%3,%4};"
                 :: "l"(addr), "f"(a), "f"(b), "f"(c), "f"(d) : "memory");
}
// accumulate 8 half-channels from one uint4
__device__ __forceinline__ void acc_h8(float* s, uint4 u) {
    float2 f0 = __half22float2(*(__half2*)&u.x);
    float2 f1 = __half22float2(*(__half2*)&u.y);
    float2 f2 = __half22float2(*(__half2*)&u.z);
    float2 f3 = __half22float2(*(__half2*)&u.w);
    s[0] += f0.x; s[1] += f0.y; s[2] += f1.x; s[3] += f1.y;
    s[4] += f2.x; s[5] += f2.y; s[6] += f3.x; s[7] += f3.y;
}

// ---------------- CSR build ---------------------------------------------------
// 2 edges per thread, int2 loads
__global__ void k_hist(const int* __restrict__ ei) {
    int e2 = blockIdx.x * blockDim.x + threadIdx.x;
    if (e2 * 2 < EE) {
        int2 d2 = *(const int2*)&ei[EE + e2 * 2];
        atomicAdd(&g_cnt[d2.x], 1);
        atomicAdd(&g_cnt[d2.y], 1);
    }
}
__global__ void k_scanA() {
    __shared__ int sh[256];
    int i = blockIdx.x * 256 + threadIdx.x;
    sh[threadIdx.x] = (i < NN) ? g_cnt[i] : 0;
    __syncthreads();
    for (int o = 128; o > 0; o >>= 1) {
        if (threadIdx.x < o) sh[threadIdx.x] += sh[threadIdx.x + o];
        __syncthreads();
    }
    if (threadIdx.x == 0) g_bsum[blockIdx.x] = sh[0];
}
__global__ void k_scanB() {
    __shared__ int sh[256];
    int t = threadIdx.x;
    int v = (t < SCAN_B) ? g_bsum[t] : 0;
    sh[t] = v;
    __syncthreads();
    for (int o = 1; o < 256; o <<= 1) {
        int u = (t >= o) ? sh[t - o] : 0;
        __syncthreads();
        sh[t] += u;
        __syncthreads();
    }
    if (t < SCAN_B) g_bsum[t] = sh[t] - v;
    if (t == 0) g_rowptr[NN] = EE;
}
__global__ void k_scanC(const float* __restrict__ x) {
    __shared__ int sh[256];
    int i = blockIdx.x * 256 + threadIdx.x;
    int t = threadIdx.x;
    int c = (i < NN) ? g_cnt[i] : 0;
    sh[t] = c;
    __syncthreads();
    for (int o = 1; o < 256; o <<= 1) {
        int u = (t >= o) ? sh[t - o] : 0;
        __syncthreads();
        sh[t] += u;
        __syncthreads();
    }
    if (i < NN) {
        int rp = g_bsum[blockIdx.x] + sh[t] - c;
        g_rowptr[i] = rp;
        g_cur[i]    = rp;
        float d = rsqrtf((float)c + 1.0f);
        g_dis[i]  = d;
        g_td[i]   = make_float2(x[i] * d, d);
    }
}
// 2 edges per thread, int2 loads
__global__ void k_fill(const int* __restrict__ ei) {
    int e2 = blockIdx.x * blockDim.x + threadIdx.x;
    if (e2 * 2 < EE) {
        int2 s2 = *(const int2*)&ei[e2 * 2];
        int2 d2 = *(const int2*)&ei[EE + e2 * 2];
        int p0 = atomicAdd(&g_cur[d2.x], 1);
        g_csr[p0] = s2.x;
        int p1 = atomicAdd(&g_cur[d2.y], 1);
        g_csr[p1] = s2.y;
    }
}

// ---------------- layer 0 (frozen: proven R11/R14/R15 version) -----------------
__global__ void k_l0(const float* __restrict__ W1, const float* __restrict__ b1,
                     float* __restrict__ statsOut) {
    int n = blockIdx.x * 256 + threadIdx.x;
    bool valid = n < NN;
    float u = 0.f, d = 0.f;
    if (valid) {
        float2 self = g_td[n];
        d = self.y;
        float st = self.x, sd = self.y;
        int j = g_rowptr[n], end = g_rowptr[n + 1];
        while (j < end && (j & 3)) { float2 a = g_td[g_csr[j++]]; st += a.x; sd += a.y; }
        for (; j + 4 <= end; j += 4) {
            int4 i4 = *(const int4*)&g_csr[j];
            float2 a0 = g_td[i4.x], a1 = g_td[i4.y], a2 = g_td[i4.z], a3 = g_td[i4.w];
            st += (a0.x + a1.x) + (a2.x + a3.x);
            sd += (a0.y + a1.y) + (a2.y + a3.y);
        }
        for (; j < end; ++j) { float2 a = g_td[g_csr[j]]; st += a.x; sd += a.y; }
        u = d * st;
        g_rs[n] = d * sd;
    }
    float sm[16], sq[16], vv[16];
    #pragma unroll
    for (int c = 0; c < 16; ++c) {
        float v = valid ? geluf(fmaf(__ldg(&W1[c]), u, __ldg(&b1[c]))) : 0.f;
        vv[c] = v; sm[c] = v; sq[c] = v * v;
    }
    if (valid) {
        uint4 o0, o1;
        __half2 h;
        h = __floats2half2_rn(vv[0]*d,  vv[1]*d);  o0.x = *(unsigned*)&h;
        h = __floats2half2_rn(vv[2]*d,  vv[3]*d);  o0.y = *(unsigned*)&h;
        h = __floats2half2_rn(vv[4]*d,  vv[5]*d);  o0.z = *(unsigned*)&h;
        h = __floats2half2_rn(vv[6]*d,  vv[7]*d);  o0.w = *(unsigned*)&h;
        h = __floats2half2_rn(vv[8]*d,  vv[9]*d);  o1.x = *(unsigned*)&h;
        h = __floats2half2_rn(vv[10]*d, vv[11]*d); o1.y = *(unsigned*)&h;
        h = __floats2half2_rn(vv[12]*d, vv[13]*d); o1.z = *(unsigned*)&h;
        h = __floats2half2_rn(vv[14]*d, vv[15]*d); o1.w = *(unsigned*)&h;
        ((uint4*)&g_ya[n * 16])[0] = o0;
        ((uint4*)&g_ya[n * 16])[1] = o1;
    }
    #pragma unroll
    for (int off = 16; off > 0; off >>= 1) {
        #pragma unroll
        for (int c = 0; c < 16; ++c) {
            sm[c] += __shfl_xor_sync(0xffffffffu, sm[c], off);
            sq[c] += __shfl_xor_sync(0xffffffffu, sq[c], off);
        }
    }
    if ((threadIdx.x & 31) == 0) {
        #pragma unroll
        for (int c = 0; c < 16; ++c) {
            atomicAdd(&statsOut[c], sm[c]);
            atomicAdd(&statsOut[16 + c], sq[c]);
        }
    }
}

// ---------------- fused layer (frozen R15): uint4 gather -> W-hoisted mm -------
template<int Cin, int Cout, int TILE, bool POOL>
__global__ void __launch_bounds__(256) k_layer(
        const __half* __restrict__ yin, __half* __restrict__ yout,
        const float* __restrict__ W, const float* __restrict__ bias,
        const float* __restrict__ gam, const float* __restrict__ bet,
        const float* __restrict__ statsIn, float* __restrict__ statsOut,
        const int* __restrict__ batch) {
    const int WQ8   = Cin / 8;           // uint4 groups per node row
    const int CQ    = Cout / 4;
    const int TPN   = 2 * WQ8;           // threads per node in gather
    const int NPB_A = 256 / TPN;         // nodes per gather pass
    const int PASSES = TILE / NPB_A;
    const int SLOTS = 256 / CQ;          // concurrent nodes in mm
    const int NITER = TILE / SLOTS;      // nodes per thread in mm
    __shared__ float sc[64], shf[64], sh[256];
    __shared__ float ut[TILE * Cin];     // <= 8 KB
    int tid = threadIdx.x;
    if (tid < Cin) {
        float mu  = statsIn[tid] * (1.0f / NN);
        float var = statsIn[Cin + tid] * (1.0f / NN) - mu * mu;
        float s = gam[tid] * rsqrtf(var + EPSF);
        sc[tid]  = s;
        shf[tid] = bet[tid] - mu * s;
    }
    if (!POOL) for (int i = tid; i < 2 * Cout; i += 256) sh[i] = 0.f;
    __syncthreads();

    int n0 = blockIdx.x * TILE;
    // ---- phase A: cooperative gather into ut (uint4 loads, 2-way edge split) --
    {
        int nodeA = tid / TPN;
        int rem   = tid - nodeA * TPN;
        int q8 = rem >> 1, k = rem & 1;
        const uint4* __restrict__ hw = (const uint4*)yin;
        #pragma unroll
        for (int p = 0; p < PASSES; ++p) {
            int nl = p * NPB_A + nodeA;
            int n  = n0 + nl;
            float s[8];
            #pragma unroll
            for (int c = 0; c < 8; ++c) s[c] = 0.f;
            if (n < NN) {
                int rp = g_rowptr[n], re = g_rowptr[n + 1];
                int half = (re - rp) >> 1;
                int j    = k ? (rp + half) : rp;
                int jend = k ? re : (rp + half);
                if (k == 0) acc_h8(s, hw[n * WQ8 + q8]);   // self term
                while (j < jend && (j & 3)) acc_h8(s, hw[g_csr[j++] * WQ8 + q8]);
                for (; j + 4 <= jend; j += 4) {
                    int4 a4 = *(const int4*)&g_csr[j];
                    uint4 u0 = hw[a4.x * WQ8 + q8];
                    uint4 u1 = hw[a4.y * WQ8 + q8];
                    uint4 u2 = hw[a4.z * WQ8 + q8];
                    uint4 u3 = hw[a4.w * WQ8 + q8];
                    acc_h8(s, u0); acc_h8(s, u1); acc_h8(s, u2); acc_h8(s, u3);
                }
                for (; j < jend; ++j) acc_h8(s, hw[g_csr[j] * WQ8 + q8]);
            }
            // combine the two edge-halves (lanes 2m, 2m+1)
            #pragma unroll
            for (int c = 0; c < 8; ++c)
                s[c] += __shfl_down_sync(0xffffffffu, s[c], 1);
            if (k == 0 && n < NN) {
                int ci = q8 * 8;
                float d = g_dis[n], rsv = g_rs[n];
                float* u = &ut[nl * Cin + ci];
                #pragma unroll
                for (int c = 0; c < 8; ++c)
                    u[c] = fmaf(shf[ci + c], rsv, sc[ci + c] * (s[c] * d));
            } else if (k == 0) {
                int ci = q8 * 8;
                float* u = &ut[nl * Cin + ci];
                #pragma unroll
                for (int c = 0; c < 8; ++c) u[c] = 0.f;
            }
        }
    }
    __syncthreads();

    // ---- phase B: W-hoisted mm over NITER nodes per thread ----
    int c4 = tid % CQ, slot = tid / CQ;
    const float4* __restrict__ Wv = (const float4*)W;
    float4 bb = *(const float4*)&bias[c4 * 4];
    float4 acc[NITER];
    #pragma unroll
    for (int k = 0; k < NITER; ++k) acc[k] = bb;
    #pragma unroll 4
    for (int i = 0; i < Cin; ++i) {
        float4 w = Wv[i * CQ + c4];
        #pragma unroll
        for (int k = 0; k < NITER; ++k) {
            float av = ut[(slot + k * SLOTS) * Cin + i];
            acc[k].x = fmaf(av, w.x, acc[k].x);
            acc[k].y = fmaf(av, w.y, acc[k].y);
            acc[k].z = fmaf(av, w.z, acc[k].z);
            acc[k].w = fmaf(av, w.w, acc[k].w);
        }
    }
    float4 rsum = make_float4(0.f, 0.f, 0.f, 0.f);
    float4 r2sum = make_float4(0.f, 0.f, 0.f, 0.f);
    #pragma unroll
    for (int k = 0; k < NITER; ++k) {
        int n = n0 + slot + k * SLOTS;
        if (n >= NN) continue;
        float4 r;
        r.x = geluf(acc[k].x); r.y = geluf(acc[k].y);
        r.z = geluf(acc[k].z); r.w = geluf(acc[k].w);
        if (POOL) {
            int g = batch[n];
            red_add_v4(&g_pool[g * 128 + c4 * 4], r.x, r.y, r.z, r.w);
        } else {
            float d = g_dis[n];
            __half2 h0 = __floats2half2_rn(r.x * d, r.y * d);
            __half2 h1 = __floats2half2_rn(r.z * d, r.w * d);
            uint2 u; u.x = *(unsigned*)&h0; u.y = *(unsigned*)&h1;
            ((uint2*)yout)[n * CQ + c4] = u;
            rsum.x += r.x; rsum.y += r.y; rsum.z += r.z; rsum.w += r.w;
            r2sum.x += r.x * r.x; r2sum.y += r.y * r.y;
            r2sum.z += r.z * r.z; r2sum.w += r.w * r.w;
        }
    }
    if (!POOL) {
        #pragma unroll
        for (int off = CQ; off < 32; off <<= 1) {
            rsum.x  += __shfl_down_sync(0xffffffffu, rsum.x,  off);
            rsum.y  += __shfl_down_sync(0xffffffffu, rsum.y,  off);
            rsum.z  += __shfl_down_sync(0xffffffffu, rsum.z,  off);
            rsum.w  += __shfl_down_sync(0xffffffffu, rsum.w,  off);
            r2sum.x += __shfl_down_sync(0xffffffffu, r2sum.x, off);
            r2sum.y += __shfl_down_sync(0xffffffffu, r2sum.y, off);
            r2sum.z += __shfl_down_sync(0xffffffffu, r2sum.z, off);
            r2sum.w += __shfl_down_sync(0xffffffffu, r2sum.w, off);
        }
        if ((tid & 31) < CQ) {
            int c0 = (tid % CQ) * 4;
            atomicAdd(&sh[c0 + 0], rsum.x);  atomicAdd(&sh[Cout + c0 + 0], r2sum.x);
            atomicAdd(&sh[c0 + 1], rsum.y);  atomicAdd(&sh[Cout + c0 + 1], r2sum.y);
            atomicAdd(&sh[c0 + 2], rsum.z);  atomicAdd(&sh[Cout + c0 + 2], r2sum.z);
            atomicAdd(&sh[c0 + 3], rsum.w);  atomicAdd(&sh[Cout + c0 + 3], r2sum.w);
        }
        __syncthreads();
        for (int i = tid; i < 2 * Cout; i += 256) atomicAdd(&statsOut[i], sh[i]);
    }
}

// ---------------- fused MLP head -------------------------------------------------
__global__ void k_head(const int* __restrict__ batch, const float* __restrict__ yx,
                       const float* __restrict__ lw1, const float* __restrict__ lb1,
                       const float* __restrict__ lw2, const float* __restrict__ lb2,
                       const float* __restrict__ lw3, const float* __restrict__ lb3,
                       const float* __restrict__ lw4, const float* __restrict__ lb4,
                       float* __restrict__ out) {
    int g = blockIdx.x, tid = threadIdx.x;
    __shared__ float z[136], a1[128], a2[64], a3[32];
    __shared__ int bounds[2];
    if (tid < 2) {
        int key = g + tid;
        int lo = 0, hi = NN;
        while (lo < hi) {
            int mid = (lo + hi) >> 1;
            if (batch[mid] < key) lo = mid + 1; else hi = mid;
        }
        bounds[tid] = lo;
    }
    __syncthreads();
    float inv = 1.0f / fmaxf((float)(bounds[1] - bounds[0]), 1.0f);
    for (int j = tid; j < 135; j += 128)
        z[j] = (j < 128) ? g_pool[g * 128 + j] * inv : yx[g * 7 + (j - 128)];
    __syncthreads();
    {
        float s = lb1[tid];
        #pragma unroll 5
        for (int i = 0; i < 135; ++i) s = fmaf(z[i], lw1[i * 128 + tid], s);
        a1[tid] = geluf(s);
    }
    __syncthreads();
    if (tid < 64) {
        float s = lb2[tid];
        #pragma unroll 8
        for (int i = 0; i < 128; ++i) s = fmaf(a1[i], lw2[i * 64 + tid], s);
        a2[tid] = geluf(s);
    }
    __syncthreads();
    if (tid < 32) {
        float s = lb3[tid];
        #pragma unroll 8
        for (int i = 0; i < 64; ++i) s = fmaf(a2[i], lw3[i * 32 + tid], s);
        a3[tid] = geluf(s);
    }
    __syncthreads();
    if (tid < 2) {
        float s = lb4[tid];
        #pragma unroll
        for (int i = 0; i < 32; ++i) s = fmaf(a3[i], lw4[i * 2 + tid], s);
        out[g * 2 + tid] = 1.0f / (1.0f + expf(-s));
    }
}

// ---------------- host -------------------------------------------------------------
static inline int gs(int n) { return (n + 255) / 256; }

extern "C" void kernel_launch(void* const* d_in, const int* in_sizes, int n_in,
                              void* d_out, int out_size) {
    const float* x     = (const float*)d_in[0];
    const int*   ei    = (const int*)d_in[1];
    const int*   batch = (const int*)d_in[2];
    const float* yx    = (const float*)d_in[3];
    const float* W[4]  = {(const float*)d_in[4], (const float*)d_in[6],
                          (const float*)d_in[8], (const float*)d_in[10]};
    const float* B[4]  = {(const float*)d_in[5], (const float*)d_in[7],
                          (const float*)d_in[9], (const float*)d_in[11]};
    const float* Gm[3] = {(const float*)d_in[12], (const float*)d_in[14], (const float*)d_in[16]};
    const float* Be[3] = {(const float*)d_in[13], (const float*)d_in[15], (const float*)d_in[17]};
    const float* LW[4] = {(const float*)d_in[18], (const float*)d_in[20],
                          (const float*)d_in[22], (const float*)d_in[24]};
    const float* LB[4] = {(const float*)d_in[19], (const float*)d_in[21],
                          (const float*)d_in[23], (const float*)d_in[25]};

    void *p_cnt, *p_pool, *p_stats, *p_ya, *p_yb;
    cudaGetSymbolAddress(&p_cnt,   g_cnt);
    cudaGetSymbolAddress(&p_pool,  g_pool);
    cudaGetSymbolAddress(&p_stats, g_stats);
    cudaGetSymbolAddress(&p_ya,    g_ya);
    cudaGetSymbolAddress(&p_yb,    g_yb);
    float* stats = (float*)p_stats;
    __half* ya = (__half*)p_ya;
    __half* yb = (__half*)p_yb;

    cudaMemsetAsync(p_cnt,   0, NN * sizeof(int));
    cudaMemsetAsync(p_pool,  0, GG * 128 * sizeof(float));
    cudaMemsetAsync(p_stats, 0, 384 * sizeof(float));

    k_hist <<<gs(EE / 2), 256>>>(ei);
    k_scanA<<<SCAN_B, 256>>>();
    k_scanB<<<1, 256>>>();
    k_scanC<<<SCAN_B, 256>>>(x);
    k_fill <<<gs(EE / 2), 256>>>(ei);

    // layer 0: scalar gather -> ya fp16[16] + rs + stats0
    k_l0<<<gs(NN), 256>>>(W[0], B[0], stats + 0);

    // fused layers, uint4 gathers (ping-pong message buffers)
    k_layer<16, 32, 64, false><<<(NN + 63) / 64, 256>>>(ya, yb, W[1], B[1], Gm[0], Be[0],
                                                        stats + 0, stats + 128, batch);
    k_layer<32, 64, 32, false><<<(NN + 31) / 32, 256>>>(yb, ya, W[2], B[2], Gm[1], Be[1],
                                                        stats + 128, stats + 256, batch);
    k_layer<64, 128, 32, true><<<(NN + 31) / 32, 256>>>(ya, yb, W[3], B[3], Gm[2], Be[2],
                                                        stats + 256, nullptr, batch);

    k_head<<<GG, 128>>>(batch, yx, LW[0], LB[0], LW[1], LB[1],
                        LW[2], LB[2], LW[3], LB[3], (float*)d_out);
}